// round 16
// baseline (speedup 1.0000x reference)
#include <cuda_runtime.h>
#include <cuda_bf16.h>
#include <math.h>
#include <cstdint>

#define HEADS 8
#define HEAD_DIM 32
#define CH 256
#define INNER 256
#define LL 2304
#define BB 4
#define TABLE_W 127     // 2*MAX_RES-1
#define BR 95           // 2*48-1
#define EPS 1e-6f
#define LOG2E 1.4426950408889634f
#define SC 0.25503486f  // (1/sqrt(32)) * log2(e)  -- folded into Q

// ---------------- scratch (device globals: no allocation allowed) ----------
__device__ __align__(128) __nv_bfloat16 g_xnb[BB*LL*CH];        // LN(x)   [b,l,c]
__device__ __align__(128) __nv_bfloat16 g_cnb[BB*LL*CH];        // LN(ctx) [b,l,c]
__device__ __align__(128) __nv_bfloat16 g_ob [BB*LL*INNER];     // attn out [b,l,c]
__device__ __align__(128) float2 g_biasP[HEADS*BR*BR];          // {bias[j],bias[j-1]}*log2e
__device__ __align__(128) __nv_bfloat16 g_qb[BB*HEADS*LL*32];   // Q (pre-scaled by SC)
__device__ __align__(128) __nv_bfloat16 g_kb[BB*HEADS*LL*32];
__device__ __align__(128) __nv_bfloat16 g_vt[BB*HEADS*32*LL];   // V^T [bh][d][l]
__device__ __align__(128) __nv_bfloat16 g_wq[CH*INNER];
__device__ __align__(128) __nv_bfloat16 g_wk[CH*INNER];
__device__ __align__(128) __nv_bfloat16 g_wv[CH*INNER];
__device__ __align__(128) __nv_bfloat16 g_wp[CH*INNER];

// ---------------- small helpers --------------------------------------------
__device__ __forceinline__ float ex2f(float x) {
    float r;
    asm("ex2.approx.f32 %0, %1;" : "=f"(r) : "f"(x));
    return r;
}
__device__ __forceinline__ uint32_t bf2(float x, float y) {
    __nv_bfloat162 t = __float22bfloat162_rn(make_float2(x, y));
    return *(uint32_t*)&t;
}
__device__ __forceinline__ void mma16816(float* c, const uint32_t* a, const uint32_t* b) {
    asm volatile(
        "mma.sync.aligned.m16n8k16.row.col.f32.bf16.bf16.f32 "
        "{%0,%1,%2,%3}, {%4,%5,%6,%7}, {%8,%9}, {%0,%1,%2,%3};"
        : "+f"(c[0]), "+f"(c[1]), "+f"(c[2]), "+f"(c[3])
        : "r"(a[0]), "r"(a[1]), "r"(a[2]), "r"(a[3]), "r"(b[0]), "r"(b[1]));
}
__device__ __forceinline__ void ldsm4(uint32_t* r, uint32_t addr) {
    asm volatile("ldmatrix.sync.aligned.m8n8.x4.shared.b16 {%0,%1,%2,%3}, [%4];"
        : "=r"(r[0]), "=r"(r[1]), "=r"(r[2]), "=r"(r[3]) : "r"(addr));
}
__device__ __forceinline__ uint32_t smem_u32(const void* p) {
    uint32_t a;
    asm("{ .reg .u64 t; cvta.to.shared.u64 t, %1; cvt.u32.u64 %0, t; }" : "=r"(a) : "l"(p));
    return a;
}
__device__ __forceinline__ void cpa16(uint32_t dst, const void* src) {
    asm volatile("cp.async.cg.shared.global [%0], [%1], 16;"
        :: "r"(dst), "l"(__cvta_generic_to_global(src)) : "memory");
}
#define CP_COMMIT() asm volatile("cp.async.commit_group;" ::: "memory")
#define CP_WAIT(n)  asm volatile("cp.async.wait_group %0;" :: "n"(n) : "memory")

// ---------------- LayerNorm over C of NCHW -> bf16 [B, L, C] (fused x/ctx) -
__global__ void ln_fused(const float* __restrict__ x, const float* __restrict__ ctx,
                         const float* __restrict__ wx, const float* __restrict__ bx,
                         const float* __restrict__ wc, const float* __restrict__ bc)
{
    __shared__ float s[CH*33];
    __shared__ float rsum[8][32];
    __shared__ float rsq[8][32];
    __shared__ float mu_s[32];
    __shared__ float rs_s[32];

    const float* in = blockIdx.z ? ctx : x;
    const float* w  = blockIdx.z ? wc : wx;
    const float* bvec = blockIdx.z ? bc : bx;
    __nv_bfloat16* out = blockIdx.z ? g_cnb : g_xnb;

    int tx = threadIdx.x & 31;
    int ty = threadIdx.x >> 5;
    int b  = blockIdx.y;
    int l0 = blockIdx.x * 32;

    const float* inb = in + (size_t)b*CH*LL + l0;
    float sm = 0.f, sq = 0.f;
    #pragma unroll 4
    for (int cg = 0; cg < 32; ++cg) {
        int c = cg*8 + ty;
        float vv = inb[(size_t)c*LL + tx];
        s[c*33 + tx] = vv;
        sm += vv; sq += vv*vv;
    }
    rsum[ty][tx] = sm; rsq[ty][tx] = sq;
    __syncthreads();
    if (threadIdx.x < 32) {
        float a = 0.f, c2 = 0.f;
        #pragma unroll
        for (int j = 0; j < 8; ++j) { a += rsum[j][threadIdx.x]; c2 += rsq[j][threadIdx.x]; }
        float mu  = a * (1.f/CH);
        float var = c2 * (1.f/CH) - mu*mu;
        mu_s[threadIdx.x] = mu;
        rs_s[threadIdx.x] = rsqrtf(var + EPS);
    }
    __syncthreads();
    __nv_bfloat16* ob = out + ((size_t)b*LL + l0)*CH;
    #pragma unroll 4
    for (int i = threadIdx.x; i < 32*CH; i += 256) {
        int p = i >> 8, c = i & 255;
        float vv = s[c*33 + p];
        ob[(size_t)p*CH + c] =
            __float2bfloat16((vv - mu_s[p]) * rs_s[p] * w[c] + bvec[c]);
    }
}

// ---------------- prep: paired rel-bias table + fp32->bf16 weights ---------
// NOTE: grid must cover max(CH*INNER, HEADS*BR*BR) = 72200.
__global__ void prep_kernel(const float* __restrict__ rel_table,
                            const float* __restrict__ Wq, const float* __restrict__ Wk,
                            const float* __restrict__ Wv, const float* __restrict__ Wp)
{
    int i = blockIdx.x*256 + threadIdx.x;
    if (i < CH*INNER) {
        g_wq[i] = __float2bfloat16(Wq[i]);
        g_wk[i] = __float2bfloat16(Wk[i]);
        g_wv[i] = __float2bfloat16(Wv[i]);
        g_wp[i] = __float2bfloat16(Wp[i]);
    }
    if (i < HEADS*BR*BR) {
        int h  = i / (BR*BR);
        int rr = i - h*(BR*BR);
        int dh = rr / BR;
        int dw = rr - dh*BR;
        float hi = rel_table[((dh + 16)*TABLE_W + dw + 16)*HEADS + h] * LOG2E;
        float lo = 0.f;
        if (rr > 0) {
            int r2 = rr - 1;
            int d2h = r2 / BR;
            int d2w = r2 - d2h*BR;
            lo = rel_table[((d2h + 16)*TABLE_W + d2w + 16)*HEADS + h] * LOG2E;
        }
        g_biasP[i] = make_float2(hi, lo);
    }
}

// ---------------- HMMA GEMM, cp.async double-buffered ----------------------
// BM=128, BN=128, BK=64. PROJ=0: fused QKV (mode = blockIdx.z 0..2).
// PROJ=1: out-projection with residual (NCHW f32).
#define HG_BOFF 18432          // B tile offset within one buffer
#define HG_BUF  36864          // one double-buffer slot (A+B tiles)
#define HG_DYN  73728          // 2 buffers; transpose epilogue reuses [0, 67584)
template<int PROJ>
__global__ __launch_bounds__(256) void hgemm(const float* __restrict__ bias0,
                                             const float* __restrict__ bias1,
                                             const float* __restrict__ bias2,
                                             float* __restrict__ Cout,
                                             const float* __restrict__ resid)
{
    extern __shared__ char smc[];
    int mode = PROJ ? 3 : blockIdx.z;
    const __nv_bfloat16* A  = (mode == 0) ? g_xnb : (mode == 3) ? g_ob : g_cnb;
    const __nv_bfloat16* Wb = (mode == 0) ? g_wq : (mode == 1) ? g_wk
                            : (mode == 2) ? g_wv : g_wp;
    const float* bias = PROJ ? bias0
                      : (mode == 0 ? bias0 : (mode == 1 ? bias1 : bias2));

    int tid = threadIdx.x;
    int w = tid >> 5, lane = tid & 31;
    int g = lane >> 2, tg = lane & 3;
    int m0 = blockIdx.x * 128, n0 = blockIdx.y * 128;

    // cp.async staging roles: thread -> (row, 64B half), 4x16B each of A and B
    int srow = tid >> 1, shalf = tid & 1;
    const __nv_bfloat16* agp = A  + (size_t)(m0 + srow)*256 + shalf*32;
    const __nv_bfloat16* bgp = Wb + (size_t)(n0 + srow)*256 + shalf*32;
    uint32_t sb = smem_u32(smc);
    uint32_t aDst = sb + (uint32_t)(srow*144 + shalf*64);
    uint32_t bDst = aDst + HG_BOFF;

    // ldmatrix lane bases
    int tA = lane >> 3, rA = lane & 7;
    uint32_t aBase = sb + (uint32_t)((w*16 + (tA & 1)*8 + rA)*144 + (tA >> 1)*16);
    uint32_t bBase = sb + HG_BOFF + (uint32_t)(((tA >> 1)*8 + rA)*144 + (tA & 1)*16);

    float c[16][4];
    #pragma unroll
    for (int i = 0; i < 16; ++i) { c[i][0]=c[i][1]=c[i][2]=c[i][3]=0.f; }

    // preload chunk 0 into buffer 0
    #pragma unroll
    for (int j = 0; j < 4; ++j) {
        cpa16(aDst + j*16, agp + j*8);
        cpa16(bDst + j*16, bgp + j*8);
    }
    CP_COMMIT();

    #pragma unroll
    for (int kc = 0; kc < 4; ++kc) {
        __syncthreads();                       // all prior compute done
        if (kc < 3) {
            uint32_t nb = (uint32_t)(((kc + 1) & 1) * HG_BUF);
            #pragma unroll
            for (int j = 0; j < 4; ++j) {
                cpa16(aDst + nb + j*16, agp + (kc+1)*64 + j*8);
                cpa16(bDst + nb + j*16, bgp + (kc+1)*64 + j*8);
            }
            CP_COMMIT();
            CP_WAIT(1);
        } else {
            CP_WAIT(0);
        }
        __syncthreads();                       // staged chunk kc visible

        uint32_t bo = (uint32_t)((kc & 1) * HG_BUF);
        #pragma unroll
        for (int ks = 0; ks < 4; ++ks) {
            uint32_t a[4];
            ldsm4(a, aBase + bo + ks*32);
            #pragma unroll
            for (int p = 0; p < 8; ++p) {
                uint32_t bb[4];
                ldsm4(bb, bBase + bo + p*2304 + ks*32);
                mma16816(c[2*p],     a, bb);
                mma16816(c[2*p + 1], a, bb + 2);
            }
        }
    }

    int b  = m0 / LL;                 // 128-row tiles never straddle batches
    int l0 = m0 - b*LL;
    int r0 = l0 + w*16 + g, r1 = r0 + 8;

    if (!PROJ && mode <= 1) {
        __nv_bfloat16* dst = (mode == 0) ? g_qb : g_kb;
        const float scl = (mode == 0) ? SC : 1.0f;
        #pragma unroll
        for (int nt = 0; nt < 16; ++nt) {
            int n = n0 + nt*8 + tg*2;
            float2 bb = *(const float2*)(bias + n);
            int hh = n >> 5, d0 = n & 31;
            uint32_t u0 = bf2((c[nt][0]+bb.x)*scl, (c[nt][1]+bb.y)*scl);
            uint32_t u1 = bf2((c[nt][2]+bb.x)*scl, (c[nt][3]+bb.y)*scl);
            *(uint32_t*)(&dst[((size_t)(b*8 + hh)*LL + r0)*32 + d0]) = u0;
            *(uint32_t*)(&dst[((size_t)(b*8 + hh)*LL + r1)*32 + d0]) = u1;
        }
    } else {
        // transpose through smem (reuse staging buffers)
        __syncthreads();
        float* tr = (float*)smc;
        int lr0 = w*16 + g, lr1 = lr0 + 8;
        #pragma unroll
        for (int nt = 0; nt < 16; ++nt) {
            int nl = nt*8 + tg*2;
            tr[nl*132 + lr0]       = c[nt][0];
            tr[(nl + 1)*132 + lr0] = c[nt][1];
            tr[nl*132 + lr1]       = c[nt][2];
            tr[(nl + 1)*132 + lr1] = c[nt][3];
        }
        __syncthreads();
        int n = tid >> 1, lh = (tid & 1)*64;
        int gn = n0 + n;
        float bj = bias[gn];
        const float* trp = tr + n*132 + lh;
        if (PROJ) {
            size_t ad = ((size_t)b*256 + gn)*LL + l0 + lh;
            #pragma unroll
            for (int j = 0; j < 16; ++j) {
                float4 xv = ((const float4*)(resid + ad))[j];
                float4 tv = *(const float4*)(trp + j*4);
                ((float4*)(Cout + ad))[j] = make_float4(
                    xv.x + tv.x + bj, xv.y + tv.y + bj,
                    xv.z + tv.z + bj, xv.w + tv.w + bj);
            }
        } else {  // mode 2 -> g_vt bf16 [bh][d][l]
            int hh = gn >> 5, d = gn & 31;
            __nv_bfloat16* vd = g_vt + ((size_t)(b*8 + hh)*32 + d)*LL + l0 + lh;
            #pragma unroll
            for (int j = 0; j < 8; ++j) {
                float4 t0 = *(const float4*)(trp + j*8);
                float4 t1 = *(const float4*)(trp + j*8 + 4);
                uint4 u;
                u.x = bf2(t0.x + bj, t0.y + bj);
                u.y = bf2(t0.z + bj, t0.w + bj);
                u.z = bf2(t1.x + bj, t1.y + bj);
                u.w = bf2(t1.z + bj, t1.w + bj);
                *(uint4*)(vd + j*8) = u;
            }
        }
    }
}

// ---------------- HMMA flash attention (ldmatrix + cp.async) ---------------
// grid (LL/128, BB*HEADS), 256 threads (8 warps). Warp w owns q-rows
// [l0 + w*16, +16). Keys in 64-chunks, double-buffered.
// Bias pairs read from global g_biasP (L2-resident). 4 CTAs/SM target.
// Dynamic smem layout (bytes):
#define AT_K   0        // K tiles: 2 x 64*80   = 10240
#define AT_V   10240    // V tiles: 2 x 32*144  =  9216
#define AT_KO  19456    // kOffE[LL/2] int     =  4608 (kOff of EVEN keys only)
#define AT_TOT 24064
__global__ void __launch_bounds__(256, 4) attn_hmma()
{
    extern __shared__ char sma[];

    int tid = threadIdx.x;
    int w = tid >> 5, lane = tid & 31;
    int g = lane >> 2, tg = lane & 3;
    int bh = blockIdx.y;
    int b = bh >> 3, h = bh & 7;
    int l0 = blockIdx.x * 128;

    int* kOffE = (int*)(sma + AT_KO);
    const float2* __restrict__ bp = g_biasP + h*BR*BR;

    // kOff for even keys: key = 2j never has kw == 47 (48 even), so the pair
    // (2j, 2j+1) never crosses a w-row: bias idx of 2j+1 = bias idx of 2j - 1.
    for (int j = tid; j < LL/2; j += 256) {
        int key = 2*j;
        int kh = key / 48;
        kOffE[j] = kh*BR + (key - kh*48);
    }

    int r0 = l0 + w*16 + g;
    int r1 = r0 + 8;
    uint32_t qa[2][4];
    {
        const __nv_bfloat16* q0 = g_qb + ((size_t)bh*LL + r0)*32;
        const __nv_bfloat16* q1 = q0 + 8*32;
        #pragma unroll
        for (int ks = 0; ks < 2; ++ks) {
            qa[ks][0] = *(const uint32_t*)(q0 + ks*16 + tg*2);
            qa[ks][1] = *(const uint32_t*)(q1 + ks*16 + tg*2);
            qa[ks][2] = *(const uint32_t*)(q0 + ks*16 + tg*2 + 8);
            qa[ks][3] = *(const uint32_t*)(q1 + ks*16 + tg*2 + 8);
        }
    }
    int qh0 = r0 / 48, qw0 = r0 - qh0*48;
    int qh1 = r1 / 48, qw1 = r1 - qh1*48;
    int qb0 = (qh0 + 47)*BR + qw0 + 47;     // global bias row index
    int qb1 = (qh1 + 47)*BR + qw1 + 47;

    float o[4][4];
    #pragma unroll
    for (int i = 0; i < 4; ++i) { o[i][0]=o[i][1]=o[i][2]=o[i][3]=0.f; }
    float ls0 = 0.f, ls1 = 0.f;

    const __nv_bfloat16* kg = g_kb + (size_t)bh*LL*32;
    const __nv_bfloat16* vg = g_vt + (size_t)bh*32*LL;

    // cp.async roles: 1 x 16B per thread for K and V each
    int kkey = tid >> 2, kseg = tid & 3;
    int vd   = tid >> 3, vseg = tid & 7;
    uint32_t kDst = smem_u32(sma + AT_K) + (uint32_t)(kkey*80 + kseg*16);
    uint32_t vDst = smem_u32(sma + AT_V) + (uint32_t)(vd*144 + vseg*16);

    // ldmatrix lane bases: lane = t*8 + r -> tile t, row r
    int t4 = lane >> 3, r8 = lane & 7;
    uint32_t kAdr0 = smem_u32(sma + AT_K) + (uint32_t)((8*(t4 >> 1) + r8)*80  + (t4 & 1)*16);
    uint32_t vAdr0 = smem_u32(sma + AT_V) + (uint32_t)((8*(t4 >> 1) + r8)*144 + (t4 & 1)*16);

    // preload chunk 0
    cpa16(kDst, kg + (size_t)kkey*32 + kseg*8);
    cpa16(vDst, vg + (size_t)vd*LL + vseg*8);
    CP_COMMIT();

    for (int kt = 0; kt < LL/64; ++kt) {
        int cur = kt & 1;
        __syncthreads();                       // prev compute done everywhere
        if (kt < LL/64 - 1) {
            uint32_t nxt = (uint32_t)(cur ^ 1);
            cpa16(kDst + nxt*5120, kg + (size_t)((kt+1)*64 + kkey)*32 + kseg*8);
            cpa16(vDst + nxt*4608, vg + (size_t)vd*LL + (kt+1)*64 + vseg*8);
            CP_COMMIT();
            CP_WAIT(1);
        } else {
            CP_WAIT(0);
        }
        __syncthreads();                       // chunk kt visible to all

        uint32_t kAdr = kAdr0 + (uint32_t)(cur*5120);
        uint32_t vAdr = vAdr0 + (uint32_t)(cur*4608);

        // ---- S = Q K^T fused with softmax per ntp (keeps S live-range small)
        uint32_t pa[4][4];
        int koIdx = kt*32 + tg;                // index into kOffE (even keys)
        #pragma unroll
        for (int ntp = 0; ntp < 4; ++ntp) {
            // prefetch bias pairs for both n-tiles of this ntp (L2)
            int ko0 = kOffE[koIdx + 8*ntp];
            int ko1 = kOffE[koIdx + 8*ntp + 4];
            float2 b00 = bp[qb0 - ko0];
            float2 b01 = bp[qb1 - ko0];
            float2 b10 = bp[qb0 - ko1];
            float2 b11 = bp[qb1 - ko1];

            float S0[4] = {0.f, 0.f, 0.f, 0.f};
            float S1[4] = {0.f, 0.f, 0.f, 0.f};
            #pragma unroll
            for (int ks = 0; ks < 2; ++ks) {
                uint32_t bb[4];
                ldsm4(bb, kAdr + ntp*1280 + ks*32);
                mma16816(S0, qa[ks], bb);
                mma16816(S1, qa[ks], bb + 2);
            }

            float p0 = ex2f(S0[0] + b00.x);
            float p1 = ex2f(S0[1] + b00.y);
            float p2 = ex2f(S0[2] + b01.x);
            float p3 = ex2f(S0[3] + b01.y);
            ls0 += p0 + p1;
            ls1 += p2 + p3;
            pa[ntp][0] = bf2(p0, p1);
            pa[ntp][1] = bf2(p2, p3);

            float q0 = ex2f(S1[0] + b10.x);
            float q1 = ex2f(S1[1] + b10.y);
            float q2 = ex2f(S1[2] + b11.x);
            float q3 = ex2f(S1[3] + b11.y);
            ls0 += q0 + q1;
            ls1 += q2 + q3;
            pa[ntp][2] = bf2(q0, q1);
            pa[ntp][3] = bf2(q2, q3);
        }

        // ---- O += P V : 8 ldsm.x4 + 16 HMMA
        #pragma unroll
        for (int ntp = 0; ntp < 2; ++ntp) {
            #pragma unroll
            for (int ks = 0; ks < 4; ++ks) {
                uint32_t bb[4];
                ldsm4(bb, vAdr + ntp*2304 + ks*32);
                mma16816(o[2*ntp],     pa[ks], bb);
                mma16816(o[2*ntp + 1], pa[ks], bb + 2);
            }
        }
    }

    ls0 += __shfl_xor_sync(0xFFFFFFFFu, ls0, 1);
    ls0 += __shfl_xor_sync(0xFFFFFFFFu, ls0, 2);
    ls1 += __shfl_xor_sync(0xFFFFFFFFu, ls1, 1);
    ls1 += __shfl_xor_sync(0xFFFFFFFFu, ls1, 2);
    float rd0 = 1.f / ls0, rd1 = 1.f / ls1;

    __nv_bfloat16* o0 = g_ob + ((size_t)b*LL + r0)*256 + h*32 + tg*2;
    __nv_bfloat16* o1 = g_ob + ((size_t)b*LL + r1)*256 + h*32 + tg*2;
    #pragma unroll
    for (int nt = 0; nt < 4; ++nt) {
        *(uint32_t*)(o0 + nt*8) = bf2(o[nt][0]*rd0, o[nt][1]*rd0);
        *(uint32_t*)(o1 + nt*8) = bf2(o[nt][2]*rd1, o[nt][3]*rd1);
    }
}

// ---------------------------------------------------------------------------
extern "C" void kernel_launch(void* const* d_in, const int* in_sizes, int n_in,
                              void* d_out, int out_size)
{
    const float* x      = (const float*)d_in[0];
    const float* ctx    = (const float*)d_in[1];
    const float* ln_x_w = (const float*)d_in[2];
    const float* ln_x_b = (const float*)d_in[3];
    const float* ln_c_w = (const float*)d_in[4];
    const float* ln_c_b = (const float*)d_in[5];
    const float* Wq     = (const float*)d_in[6];
    const float* bq     = (const float*)d_in[7];
    const float* Wk     = (const float*)d_in[8];
    const float* bk     = (const float*)d_in[9];
    const float* Wv     = (const float*)d_in[10];
    const float* bv     = (const float*)d_in[11];
    const float* Wp     = (const float*)d_in[12];
    const float* bp     = (const float*)d_in[13];
    const float* rel    = (const float*)d_in[14];
    float* out = (float*)d_out;

    cudaFuncSetAttribute(hgemm<0>, cudaFuncAttributeMaxDynamicSharedMemorySize, HG_DYN);
    cudaFuncSetAttribute(hgemm<1>, cudaFuncAttributeMaxDynamicSharedMemorySize, HG_DYN);
    cudaFuncSetAttribute(attn_hmma, cudaFuncAttributeMaxDynamicSharedMemorySize, AT_TOT);

    ln_fused<<<dim3(LL/32, BB, 2), 256>>>(x, ctx, ln_x_w, ln_x_b, ln_c_w, ln_c_b);
    prep_kernel<<<(HEADS*BR*BR + 255)/256, 256>>>(rel, Wq, Wk, Wv, Wp);

    hgemm<0><<<dim3(BB*LL/128, INNER/128, 3), 256, HG_DYN>>>(bq, bk, bv, nullptr, nullptr);

    attn_hmma<<<dim3(LL/128, BB*HEADS), 256, AT_TOT>>>();

    hgemm<1><<<dim3(BB*LL/128, INNER/128), 256, HG_DYN>>>(bp, nullptr, nullptr, out, x);
}

// round 17
// speedup vs baseline: 1.0669x; 1.0669x over previous
#include <cuda_runtime.h>
#include <cuda_bf16.h>
#include <math.h>
#include <cstdint>

#define HEADS 8
#define HEAD_DIM 32
#define CH 256
#define INNER 256
#define LL 2304
#define BB 4
#define TABLE_W 127     // 2*MAX_RES-1
#define BR 95           // 2*48-1
#define EPS 1e-6f
#define LOG2E 1.4426950408889634f
#define SC 0.25503486f  // (1/sqrt(32)) * log2(e)  -- folded into Q
#define NSPLIT 2
#define KCH (LL/64/NSPLIT)   // 18 key-chunks per split

// ---------------- scratch (device globals: no allocation allowed) ----------
__device__ __align__(128) __nv_bfloat16 g_xnb[BB*LL*CH];        // LN(x)   [b,l,c]
__device__ __align__(128) __nv_bfloat16 g_cnb[BB*LL*CH];        // LN(ctx) [b,l,c]
__device__ __align__(128) __nv_bfloat16 g_ob [BB*LL*INNER];     // attn out [b,l,c]
__device__ float g_biasc[HEADS*BR*BR];                          // bias * log2e
__device__ __align__(128) __nv_bfloat16 g_qb[BB*HEADS*LL*32];   // Q (pre-scaled by SC)
__device__ __align__(128) __nv_bfloat16 g_kb[BB*HEADS*LL*32];
__device__ __align__(128) __nv_bfloat16 g_vt[BB*HEADS*32*LL];   // V^T [bh][d][l]
__device__ __align__(128) __nv_bfloat16 g_wq[CH*INNER];
__device__ __align__(128) __nv_bfloat16 g_wk[CH*INNER];
__device__ __align__(128) __nv_bfloat16 g_wv[CH*INNER];
__device__ __align__(128) __nv_bfloat16 g_wp[CH*INNER];
__device__ __align__(128) float g_part[NSPLIT*BB*HEADS*LL*32];  // partial O (unnormalized)
__device__ __align__(128) float g_pls [NSPLIT*BB*HEADS*LL];     // partial row sums

// ---------------- small helpers --------------------------------------------
__device__ __forceinline__ float ex2f(float x) {
    float r;
    asm("ex2.approx.f32 %0, %1;" : "=f"(r) : "f"(x));
    return r;
}
__device__ __forceinline__ uint32_t bf2(float x, float y) {
    __nv_bfloat162 t = __float22bfloat162_rn(make_float2(x, y));
    return *(uint32_t*)&t;
}
__device__ __forceinline__ void mma16816(float* c, const uint32_t* a, const uint32_t* b) {
    asm volatile(
        "mma.sync.aligned.m16n8k16.row.col.f32.bf16.bf16.f32 "
        "{%0,%1,%2,%3}, {%4,%5,%6,%7}, {%8,%9}, {%0,%1,%2,%3};"
        : "+f"(c[0]), "+f"(c[1]), "+f"(c[2]), "+f"(c[3])
        : "r"(a[0]), "r"(a[1]), "r"(a[2]), "r"(a[3]), "r"(b[0]), "r"(b[1]));
}
__device__ __forceinline__ void ldsm4(uint32_t* r, uint32_t addr) {
    asm volatile("ldmatrix.sync.aligned.m8n8.x4.shared.b16 {%0,%1,%2,%3}, [%4];"
        : "=r"(r[0]), "=r"(r[1]), "=r"(r[2]), "=r"(r[3]) : "r"(addr));
}
__device__ __forceinline__ uint32_t smem_u32(const void* p) {
    uint32_t a;
    asm("{ .reg .u64 t; cvta.to.shared.u64 t, %1; cvt.u32.u64 %0, t; }" : "=r"(a) : "l"(p));
    return a;
}
__device__ __forceinline__ void cpa16(uint32_t dst, const void* src) {
    asm volatile("cp.async.cg.shared.global [%0], [%1], 16;"
        :: "r"(dst), "l"(__cvta_generic_to_global(src)) : "memory");
}
#define CP_COMMIT() asm volatile("cp.async.commit_group;" ::: "memory")
#define CP_WAIT(n)  asm volatile("cp.async.wait_group %0;" :: "n"(n) : "memory")

// ---------------- LayerNorm over C of NCHW -> bf16 [B, L, C] (fused x/ctx) -
__global__ void ln_fused(const float* __restrict__ x, const float* __restrict__ ctx,
                         const float* __restrict__ wx, const float* __restrict__ bx,
                         const float* __restrict__ wc, const float* __restrict__ bc)
{
    __shared__ float s[CH*33];
    __shared__ float rsum[8][32];
    __shared__ float rsq[8][32];
    __shared__ float mu_s[32];
    __shared__ float rs_s[32];

    const float* in = blockIdx.z ? ctx : x;
    const float* w  = blockIdx.z ? wc : wx;
    const float* bvec = blockIdx.z ? bc : bx;
    __nv_bfloat16* out = blockIdx.z ? g_cnb : g_xnb;

    int tx = threadIdx.x & 31;
    int ty = threadIdx.x >> 5;
    int b  = blockIdx.y;
    int l0 = blockIdx.x * 32;

    const float* inb = in + (size_t)b*CH*LL + l0;
    float sm = 0.f, sq = 0.f;
    #pragma unroll 4
    for (int cg = 0; cg < 32; ++cg) {
        int c = cg*8 + ty;
        float vv = inb[(size_t)c*LL + tx];
        s[c*33 + tx] = vv;
        sm += vv; sq += vv*vv;
    }
    rsum[ty][tx] = sm; rsq[ty][tx] = sq;
    __syncthreads();
    if (threadIdx.x < 32) {
        float a = 0.f, c2 = 0.f;
        #pragma unroll
        for (int j = 0; j < 8; ++j) { a += rsum[j][threadIdx.x]; c2 += rsq[j][threadIdx.x]; }
        float mu  = a * (1.f/CH);
        float var = c2 * (1.f/CH) - mu*mu;
        mu_s[threadIdx.x] = mu;
        rs_s[threadIdx.x] = rsqrtf(var + EPS);
    }
    __syncthreads();
    __nv_bfloat16* ob = out + ((size_t)b*LL + l0)*CH;
    #pragma unroll 4
    for (int i = threadIdx.x; i < 32*CH; i += 256) {
        int p = i >> 8, c = i & 255;
        float vv = s[c*33 + p];
        ob[(size_t)p*CH + c] =
            __float2bfloat16((vv - mu_s[p]) * rs_s[p] * w[c] + bvec[c]);
    }
}

// ---------------- prep: rel-bias compaction + fp32->bf16 weights -----------
// NOTE: grid must cover max(CH*INNER, HEADS*BR*BR) = 72200.
__global__ void prep_kernel(const float* __restrict__ rel_table,
                            const float* __restrict__ Wq, const float* __restrict__ Wk,
                            const float* __restrict__ Wv, const float* __restrict__ Wp)
{
    int i = blockIdx.x*256 + threadIdx.x;
    if (i < CH*INNER) {
        g_wq[i] = __float2bfloat16(Wq[i]);
        g_wk[i] = __float2bfloat16(Wk[i]);
        g_wv[i] = __float2bfloat16(Wv[i]);
        g_wp[i] = __float2bfloat16(Wp[i]);
    }
    if (i < HEADS*BR*BR) {
        int h  = i / (BR*BR);
        int rr = i - h*(BR*BR);
        int dh = rr / BR;
        int dw = rr - dh*BR;
        int idx = (dh + 16)*TABLE_W + (dw + 16);
        g_biasc[i] = rel_table[idx*HEADS + h] * LOG2E;
    }
}

// ---------------- HMMA GEMM, cp.async double-buffered ----------------------
// BM=128, BN=128, BK=64. PROJ=0: fused QKV (mode = blockIdx.z 0..2).
// PROJ=1: out-projection with residual (NCHW f32).
#define HG_BOFF 18432          // B tile offset within one buffer
#define HG_BUF  36864          // one double-buffer slot (A+B tiles)
#define HG_DYN  73728          // 2 buffers; transpose epilogue reuses [0, 67584)
template<int PROJ>
__global__ __launch_bounds__(256) void hgemm(const float* __restrict__ bias0,
                                             const float* __restrict__ bias1,
                                             const float* __restrict__ bias2,
                                             float* __restrict__ Cout,
                                             const float* __restrict__ resid)
{
    extern __shared__ char smc[];
    int mode = PROJ ? 3 : blockIdx.z;
    const __nv_bfloat16* A  = (mode == 0) ? g_xnb : (mode == 3) ? g_ob : g_cnb;
    const __nv_bfloat16* Wb = (mode == 0) ? g_wq : (mode == 1) ? g_wk
                            : (mode == 2) ? g_wv : g_wp;
    const float* bias = PROJ ? bias0
                      : (mode == 0 ? bias0 : (mode == 1 ? bias1 : bias2));

    int tid = threadIdx.x;
    int w = tid >> 5, lane = tid & 31;
    int g = lane >> 2, tg = lane & 3;
    int m0 = blockIdx.x * 128, n0 = blockIdx.y * 128;

    // cp.async staging roles: thread -> (row, 64B half), 4x16B each of A and B
    int srow = tid >> 1, shalf = tid & 1;
    const __nv_bfloat16* agp = A  + (size_t)(m0 + srow)*256 + shalf*32;
    const __nv_bfloat16* bgp = Wb + (size_t)(n0 + srow)*256 + shalf*32;
    uint32_t sb = smem_u32(smc);
    uint32_t aDst = sb + (uint32_t)(srow*144 + shalf*64);
    uint32_t bDst = aDst + HG_BOFF;

    // ldmatrix lane bases
    int tA = lane >> 3, rA = lane & 7;
    uint32_t aBase = sb + (uint32_t)((w*16 + (tA & 1)*8 + rA)*144 + (tA >> 1)*16);
    uint32_t bBase = sb + HG_BOFF + (uint32_t)(((tA >> 1)*8 + rA)*144 + (tA & 1)*16);

    float c[16][4];
    #pragma unroll
    for (int i = 0; i < 16; ++i) { c[i][0]=c[i][1]=c[i][2]=c[i][3]=0.f; }

    // preload chunk 0 into buffer 0
    #pragma unroll
    for (int j = 0; j < 4; ++j) {
        cpa16(aDst + j*16, agp + j*8);
        cpa16(bDst + j*16, bgp + j*8);
    }
    CP_COMMIT();

    #pragma unroll
    for (int kc = 0; kc < 4; ++kc) {
        __syncthreads();                       // all prior compute done
        if (kc < 3) {
            uint32_t nb = (uint32_t)(((kc + 1) & 1) * HG_BUF);
            #pragma unroll
            for (int j = 0; j < 4; ++j) {
                cpa16(aDst + nb + j*16, agp + (kc+1)*64 + j*8);
                cpa16(bDst + nb + j*16, bgp + (kc+1)*64 + j*8);
            }
            CP_COMMIT();
            CP_WAIT(1);
        } else {
            CP_WAIT(0);
        }
        __syncthreads();                       // staged chunk kc visible

        uint32_t bo = (uint32_t)((kc & 1) * HG_BUF);
        #pragma unroll
        for (int ks = 0; ks < 4; ++ks) {
            uint32_t a[4];
            ldsm4(a, aBase + bo + ks*32);
            #pragma unroll
            for (int p = 0; p < 8; ++p) {
                uint32_t bb[4];
                ldsm4(bb, bBase + bo + p*2304 + ks*32);
                mma16816(c[2*p],     a, bb);
                mma16816(c[2*p + 1], a, bb + 2);
            }
        }
    }

    int b  = m0 / LL;                 // 128-row tiles never straddle batches
    int l0 = m0 - b*LL;
    int r0 = l0 + w*16 + g, r1 = r0 + 8;

    if (!PROJ && mode <= 1) {
        __nv_bfloat16* dst = (mode == 0) ? g_qb : g_kb;
        const float scl = (mode == 0) ? SC : 1.0f;
        #pragma unroll
        for (int nt = 0; nt < 16; ++nt) {
            int n = n0 + nt*8 + tg*2;
            float2 bb = *(const float2*)(bias + n);
            int hh = n >> 5, d0 = n & 31;
            uint32_t u0 = bf2((c[nt][0]+bb.x)*scl, (c[nt][1]+bb.y)*scl);
            uint32_t u1 = bf2((c[nt][2]+bb.x)*scl, (c[nt][3]+bb.y)*scl);
            *(uint32_t*)(&dst[((size_t)(b*8 + hh)*LL + r0)*32 + d0]) = u0;
            *(uint32_t*)(&dst[((size_t)(b*8 + hh)*LL + r1)*32 + d0]) = u1;
        }
    } else {
        // transpose through smem (reuse staging buffers)
        __syncthreads();
        float* tr = (float*)smc;
        int lr0 = w*16 + g, lr1 = lr0 + 8;
        #pragma unroll
        for (int nt = 0; nt < 16; ++nt) {
            int nl = nt*8 + tg*2;
            tr[nl*132 + lr0]       = c[nt][0];
            tr[(nl + 1)*132 + lr0] = c[nt][1];
            tr[nl*132 + lr1]       = c[nt][2];
            tr[(nl + 1)*132 + lr1] = c[nt][3];
        }
        __syncthreads();
        int n = tid >> 1, lh = (tid & 1)*64;
        int gn = n0 + n;
        float bj = bias[gn];
        const float* trp = tr + n*132 + lh;
        if (PROJ) {
            size_t ad = ((size_t)b*256 + gn)*LL + l0 + lh;
            #pragma unroll
            for (int j = 0; j < 16; ++j) {
                float4 xv = ((const float4*)(resid + ad))[j];
                float4 tv = *(const float4*)(trp + j*4);
                ((float4*)(Cout + ad))[j] = make_float4(
                    xv.x + tv.x + bj, xv.y + tv.y + bj,
                    xv.z + tv.z + bj, xv.w + tv.w + bj);
            }
        } else {  // mode 2 -> g_vt bf16 [bh][d][l]
            int hh = gn >> 5, d = gn & 31;
            __nv_bfloat16* vd = g_vt + ((size_t)(b*8 + hh)*32 + d)*LL + l0 + lh;
            #pragma unroll
            for (int j = 0; j < 8; ++j) {
                float4 t0 = *(const float4*)(trp + j*8);
                float4 t1 = *(const float4*)(trp + j*8 + 4);
                uint4 u;
                u.x = bf2(t0.x + bj, t0.y + bj);
                u.y = bf2(t0.z + bj, t0.w + bj);
                u.z = bf2(t1.x + bj, t1.y + bj);
                u.w = bf2(t1.z + bj, t1.w + bj);
                *(uint4*)(vd + j*8) = u;
            }
        }
    }
}

// ---------------- HMMA flash attention (split-K over key chunks) -----------
// grid (LL/128, BB*HEADS, NSPLIT), 256 threads. Split s handles key chunks
// [s*KCH, (s+1)*KCH); writes unnormalized partial O (f32) + row sums.
// Dynamic smem layout (bytes):
#define AT_K   0        // K tiles: 2 x 64*80   = 10240
#define AT_V   10240    // V tiles: 2 x 32*144  =  9216
#define AT_KO  19456    // kOffE[LL/2] int     =  4608 (kOff of EVEN keys only)
#define AT_BP  24064    // biasP[4848] float2  = 38784 ({bias[j], bias[j-1]})
#define AT_TOT 62848
__global__ void __launch_bounds__(256) attn_hmma()
{
    extern __shared__ char sma[];

    int tid = threadIdx.x;
    int w = tid >> 5, lane = tid & 31;
    int g = lane >> 2, tg = lane & 3;
    int bh = blockIdx.y;
    int s  = blockIdx.z;
    int l0 = blockIdx.x * 128;

    int* kOffE = (int*)(sma + AT_KO);
    float2* biasP = (float2*)(sma + AT_BP);

    int h = bh & 7;
    // kOff for even keys: key = 2j never has kw == 47 (48 even), so the pair
    // (2j, 2j+1) never crosses a w-row: bias idx of 2j+1 = bias idx of 2j - 1.
    for (int j = tid; j < LL/2; j += 256) {
        int key = 2*j;
        int kh = key / 48;
        kOffE[j] = kh*BR + (key - kh*48);
    }
    // paired bias sub-table for this q-tile's qh range
    int qh_min = l0 / 48;
    {
        int qh_max = (l0 + 127) / 48;
        int rows = qh_max - qh_min + 48;          // <= 51
        const float* bc = g_biasc + h*BR*BR + qh_min*BR;
        for (int i = tid; i < rows*BR; i += 256) {
            float hi = bc[i];
            float lo = (i > 0) ? bc[i-1] : 0.f;
            biasP[i] = make_float2(hi, lo);
        }
    }

    int r0 = l0 + w*16 + g;
    int r1 = r0 + 8;
    uint32_t qa[2][4];
    {
        const __nv_bfloat16* q0 = g_qb + ((size_t)bh*LL + r0)*32;
        const __nv_bfloat16* q1 = q0 + 8*32;
        #pragma unroll
        for (int ks = 0; ks < 2; ++ks) {
            qa[ks][0] = *(const uint32_t*)(q0 + ks*16 + tg*2);
            qa[ks][1] = *(const uint32_t*)(q1 + ks*16 + tg*2);
            qa[ks][2] = *(const uint32_t*)(q0 + ks*16 + tg*2 + 8);
            qa[ks][3] = *(const uint32_t*)(q1 + ks*16 + tg*2 + 8);
        }
    }
    int qh0 = r0 / 48, qw0 = r0 - qh0*48;
    int qh1 = r1 / 48, qw1 = r1 - qh1*48;
    int qb0 = (qh0 - qh_min + 47)*BR + qw0 + 47;
    int qb1 = (qh1 - qh_min + 47)*BR + qw1 + 47;

    float o[4][4];
    #pragma unroll
    for (int i = 0; i < 4; ++i) { o[i][0]=o[i][1]=o[i][2]=o[i][3]=0.f; }
    float ls0 = 0.f, ls1 = 0.f;

    const __nv_bfloat16* kg = g_kb + (size_t)bh*LL*32;
    const __nv_bfloat16* vg = g_vt + (size_t)bh*32*LL;

    // cp.async roles: 1 x 16B per thread for K and V each
    int kkey = tid >> 2, kseg = tid & 3;
    int vd   = tid >> 3, vseg = tid & 7;
    uint32_t kDst = smem_u32(sma + AT_K) + (uint32_t)(kkey*80 + kseg*16);
    uint32_t vDst = smem_u32(sma + AT_V) + (uint32_t)(vd*144 + vseg*16);

    // ldmatrix lane bases: lane = t*8 + r -> tile t, row r
    int t4 = lane >> 3, r8 = lane & 7;
    uint32_t kAdr0 = smem_u32(sma + AT_K) + (uint32_t)((8*(t4 >> 1) + r8)*80  + (t4 & 1)*16);
    uint32_t vAdr0 = smem_u32(sma + AT_V) + (uint32_t)((8*(t4 >> 1) + r8)*144 + (t4 & 1)*16);

    const int kt0 = s*KCH, kt1 = kt0 + KCH;   // kt0 even -> buffer parity matches
    // preload first chunk of this split
    cpa16(kDst, kg + (size_t)(kt0*64 + kkey)*32 + kseg*8);
    cpa16(vDst, vg + (size_t)vd*LL + kt0*64 + vseg*8);
    CP_COMMIT();

    for (int kt = kt0; kt < kt1; ++kt) {
        int cur = kt & 1;
        __syncthreads();                       // prev compute done everywhere
        if (kt < kt1 - 1) {
            uint32_t nxt = (uint32_t)(cur ^ 1);
            cpa16(kDst + nxt*5120, kg + (size_t)((kt+1)*64 + kkey)*32 + kseg*8);
            cpa16(vDst + nxt*4608, vg + (size_t)vd*LL + (kt+1)*64 + vseg*8);
            CP_COMMIT();
            CP_WAIT(1);
        } else {
            CP_WAIT(0);
        }
        __syncthreads();                       // chunk kt visible to all

        uint32_t kAdr = kAdr0 + (uint32_t)(cur*5120);
        uint32_t vAdr = vAdr0 + (uint32_t)(cur*4608);

        // ---- S = Q K^T : 8 ldsm.x4 + 16 HMMA
        float S[8][4];
        #pragma unroll
        for (int ntp = 0; ntp < 4; ++ntp) {
            S[2*ntp][0]=S[2*ntp][1]=S[2*ntp][2]=S[2*ntp][3]=0.f;
            S[2*ntp+1][0]=S[2*ntp+1][1]=S[2*ntp+1][2]=S[2*ntp+1][3]=0.f;
            #pragma unroll
            for (int ks = 0; ks < 2; ++ks) {
                uint32_t bb[4];
                ldsm4(bb, kAdr + ntp*1280 + ks*32);
                mma16816(S[2*ntp],     qa[ks], bb);
                mma16816(S[2*ntp + 1], qa[ks], bb + 2);
            }
        }

        // ---- softmax (base-2, no max-sub) + pack P fragments
        // paired bias: one LDS.64 per (q-row, key-pair)
        uint32_t pa[4][4];
        int koIdx = kt*32 + tg;                // index into kOffE (even keys)
        #pragma unroll
        for (int nt = 0; nt < 8; ++nt) {
            int ko = kOffE[koIdx + nt*4];
            float2 bp0 = biasP[qb0 - ko];      // {bias[j], bias[j-1]}
            float2 bp1 = biasP[qb1 - ko];
            float p0 = ex2f(S[nt][0] + bp0.x);
            float p1 = ex2f(S[nt][1] + bp0.y);
            float p2 = ex2f(S[nt][2] + bp1.x);
            float p3 = ex2f(S[nt][3] + bp1.y);
            ls0 += p0 + p1;
            ls1 += p2 + p3;
            pa[nt >> 1][(nt & 1)*2 + 0] = bf2(p0, p1);
            pa[nt >> 1][(nt & 1)*2 + 1] = bf2(p2, p3);
        }

        // ---- O += P V : 8 ldsm.x4 + 16 HMMA
        #pragma unroll
        for (int ntp = 0; ntp < 2; ++ntp) {
            #pragma unroll
            for (int ks = 0; ks < 4; ++ks) {
                uint32_t bb[4];
                ldsm4(bb, vAdr + ntp*2304 + ks*32);
                mma16816(o[2*ntp],     pa[ks], bb);
                mma16816(o[2*ntp + 1], pa[ks], bb + 2);
            }
        }
    }

    ls0 += __shfl_xor_sync(0xFFFFFFFFu, ls0, 1);
    ls0 += __shfl_xor_sync(0xFFFFFFFFu, ls0, 2);
    ls1 += __shfl_xor_sync(0xFFFFFFFFu, ls1, 1);
    ls1 += __shfl_xor_sync(0xFFFFFFFFu, ls1, 2);

    // write unnormalized partials (f32) + row sums
    size_t rowBase = ((size_t)s*BB*HEADS + bh)*LL;
    float* po0 = g_part + (rowBase + r0)*32 + tg*2;
    float* po1 = g_part + (rowBase + r1)*32 + tg*2;
    #pragma unroll
    for (int nt = 0; nt < 4; ++nt) {
        *(float2*)(po0 + nt*8) = make_float2(o[nt][0], o[nt][1]);
        *(float2*)(po1 + nt*8) = make_float2(o[nt][2], o[nt][3]);
    }
    if (tg == 0) {
        g_pls[rowBase + r0] = ls0;
        g_pls[rowBase + r1] = ls1;
    }
}

// ---------------- combine partials -> bf16 g_ob ----------------------------
// thread t handles 8 d-elems of one (bh,l) row. 294912 threads = 1152 blocks.
__global__ void __launch_bounds__(256) attn_combine()
{
    int t = blockIdx.x*256 + threadIdx.x;      // 0 .. 32*LL*4-1
    int row = t >> 2;                          // bh*LL + l
    int dseg = (t & 3) << 3;                   // 0,8,16,24

    float ls = g_pls[row] + g_pls[BB*HEADS*LL + row];
    float rd = 1.f / ls;

    const float* p0 = g_part + (size_t)row*32 + dseg;
    const float* p1 = g_part + ((size_t)BB*HEADS*LL + row)*32 + dseg;
    float4 a0 = *(const float4*)(p0);
    float4 a1 = *(const float4*)(p0 + 4);
    float4 b0 = *(const float4*)(p1);
    float4 b1 = *(const float4*)(p1 + 4);

    uint4 u;
    u.x = bf2((a0.x + b0.x)*rd, (a0.y + b0.y)*rd);
    u.y = bf2((a0.z + b0.z)*rd, (a0.w + b0.w)*rd);
    u.z = bf2((a1.x + b1.x)*rd, (a1.y + b1.y)*rd);
    u.w = bf2((a1.z + b1.z)*rd, (a1.w + b1.w)*rd);

    int bh = row / LL, l = row - bh*LL;
    __nv_bfloat16* dst = g_ob + ((size_t)(bh >> 3)*LL + l)*256 + (bh & 7)*32 + dseg;
    *(uint4*)dst = u;
}

// ---------------------------------------------------------------------------
extern "C" void kernel_launch(void* const* d_in, const int* in_sizes, int n_in,
                              void* d_out, int out_size)
{
    const float* x      = (const float*)d_in[0];
    const float* ctx    = (const float*)d_in[1];
    const float* ln_x_w = (const float*)d_in[2];
    const float* ln_x_b = (const float*)d_in[3];
    const float* ln_c_w = (const float*)d_in[4];
    const float* ln_c_b = (const float*)d_in[5];
    const float* Wq     = (const float*)d_in[6];
    const float* bq     = (const float*)d_in[7];
    const float* Wk     = (const float*)d_in[8];
    const float* bk     = (const float*)d_in[9];
    const float* Wv     = (const float*)d_in[10];
    const float* bv     = (const float*)d_in[11];
    const float* Wp     = (const float*)d_in[12];
    const float* bp     = (const float*)d_in[13];
    const float* rel    = (const float*)d_in[14];
    float* out = (float*)d_out;

    cudaFuncSetAttribute(hgemm<0>, cudaFuncAttributeMaxDynamicSharedMemorySize, HG_DYN);
    cudaFuncSetAttribute(hgemm<1>, cudaFuncAttributeMaxDynamicSharedMemorySize, HG_DYN);
    cudaFuncSetAttribute(attn_hmma, cudaFuncAttributeMaxDynamicSharedMemorySize, AT_TOT);

    ln_fused<<<dim3(LL/32, BB, 2), 256>>>(x, ctx, ln_x_w, ln_x_b, ln_c_w, ln_c_b);
    prep_kernel<<<(HEADS*BR*BR + 255)/256, 256>>>(rel, Wq, Wk, Wv, Wp);

    hgemm<0><<<dim3(BB*LL/128, INNER/128, 3), 256, HG_DYN>>>(bq, bk, bv, nullptr, nullptr);

    attn_hmma<<<dim3(LL/128, BB*HEADS, NSPLIT), 256, AT_TOT>>>();
    attn_combine<<<BB*HEADS*LL*4/256, 256>>>();

    hgemm<1><<<dim3(BB*LL/128, INNER/128), 256, HG_DYN>>>(bp, nullptr, nullptr, out, x);
}